// round 8
// baseline (speedup 1.0000x reference)
#include <cuda_runtime.h>

typedef unsigned long long ull;

// Problem constants
#define DN 256
#define HN 8
#define BN 32
#define SN 1024
#define NTILE 32   // s-tiles of 32 for scores / softmax stats

// Scratch (device globals; no allocation allowed)
__device__ float g_wq[HN * DN];                 // [h][d] effective query weights
__device__ float g_scores[BN * HN * SN];        // [b][h][s] raw scores
__device__ float g_mstat[BN * HN * NTILE];      // per-tile max
__device__ float g_lstat[BN * HN * NTILE];      // per-tile sum of exp(v - m_tile)
__device__ float g_xa[BN * HN * DN];            // [b][h][d] xa (atomic-accumulated)
__device__ float g_pooled[BN * HN * DN];        // [b][j] (bv-init + atomic-accumulated)

__device__ __forceinline__ float dot4(float4 a, float4 b) {
    return a.x * b.x + a.y * b.y + a.z * b.z + a.w * b.w;
}
// sm_103a packed fp32x2 FMA (2 FMA per instruction)
__device__ __forceinline__ ull ffma2(ull a, ull b, ull c) {
    ull d;
    asm("fma.rn.f32x2 %0, %1, %2, %3;" : "=l"(d) : "l"(a), "l"(b), "l"(c));
    return d;
}
__device__ __forceinline__ ull pk(float lo, float hi) {
    ull r;
    asm("mov.b64 %0, {%1, %2};" : "=l"(r) : "f"(lo), "f"(hi));
    return r;
}
__device__ __forceinline__ float2 upk(ull v) {
    float2 r;
    asm("mov.b64 {%0, %1}, %2;" : "=f"(r.x), "=f"(r.y) : "l"(v));
    return r;
}
__device__ __forceinline__ ull addf2(ull a, ull b) {
    ull d;
    asm("add.rn.f32x2 %0, %1, %2;" : "=l"(d) : "l"(a), "l"(b));
    return d;
}

// K0: Wq_eff[h][d] = sum_{d'} Wk[d][h*256+d'] * query[h][d']   (one warp per output)
__global__ void k_wq(const float* __restrict__ Wk, const float* __restrict__ query) {
    int wid = blockIdx.x * 8 + (threadIdx.x >> 5);
    int lane = threadIdx.x & 31;
    int d = wid >> 3, h = wid & 7;
    const float4* wk4 = (const float4*)(Wk + d * 2048 + h * 256);
    const float4* q4  = (const float4*)(query + h * 256);
    float v = dot4(wk4[lane], q4[lane]) + dot4(wk4[lane + 32], q4[lane + 32]);
#pragma unroll
    for (int o = 16; o; o >>= 1) v += __shfl_xor_sync(0xffffffffu, v, o);
    if (lane == 0) g_wq[h * 256 + d] = v;
}

// K1: scores + per-tile softmax stats. Also zeroes g_xa and inits g_pooled=bv
// (runs strictly before k_xapart / k_pooled in the stream).
// grid 1024 = (b * 32 + tile); block 256; thread = (s 32, dseg 8).
__global__ void k_scores(const float* __restrict__ x, const float* __restrict__ bv) {
    __shared__ float s_wq[2048];
    __shared__ float s_sc[32 * 9];
    int t = threadIdx.x;
    int b = blockIdx.x >> 5, tile = blockIdx.x & 31;

    // 1024 blocks x 16 f4 covers g_xa (zero) and g_pooled (bv init)
    if (t < 16) {
        int o = blockIdx.x * 16 + t;
        ((float4*)g_xa)[o] = make_float4(0.f, 0.f, 0.f, 0.f);
        ((float4*)g_pooled)[o] = ((const float4*)bv)[o & 511];
    }

#pragma unroll
    for (int k = 0; k < 8; k++) s_wq[k * 256 + t] = g_wq[k * 256 + t];

    int s = t >> 3, dseg = t & 7;
    const float4* xr = (const float4*)(x + (size_t)(b * 1024 + tile * 32 + s) * 256);
    float4 xv[8];
#pragma unroll
    for (int k = 0; k < 8; k++) xv[k] = xr[k * 8 + dseg];
    __syncthreads();

    float acc[8];
#pragma unroll
    for (int h = 0; h < 8; h++) {
        const float4* wr = (const float4*)(s_wq + h * 256);
        ull a0 = 0ull, a1 = 0ull;
#pragma unroll
        for (int k = 0; k < 8; k++) {
            float4 wv = wr[k * 8 + dseg];
            a0 = ffma2(pk(xv[k].x, xv[k].y), pk(wv.x, wv.y), a0);
            a1 = ffma2(pk(xv[k].z, xv[k].w), pk(wv.z, wv.w), a1);
        }
        float2 f0 = upk(a0), f1 = upk(a1);
        acc[h] = (f0.x + f0.y) + (f1.x + f1.y);
    }
#pragma unroll
    for (int o = 1; o < 8; o <<= 1)
#pragma unroll
        for (int h = 0; h < 8; h++)
            acc[h] += __shfl_xor_sync(0xffffffffu, acc[h], o);
    float v = acc[0];
#pragma unroll
    for (int h = 1; h < 8; h++) v = (dseg == h) ? acc[h] : v;

    g_scores[(b * 8 + dseg) * 1024 + tile * 32 + s] = v;
    s_sc[s * 9 + dseg] = v;
    __syncthreads();

    if (t < 8) {
        float m = -1e30f;
#pragma unroll
        for (int i = 0; i < 32; i++) m = fmaxf(m, s_sc[i * 9 + t]);
        float l = 0.f;
#pragma unroll
        for (int i = 0; i < 32; i++) l += __expf(s_sc[i * 9 + t] - m);
        g_mstat[(b * 8 + t) * 32 + tile] = m;
        g_lstat[(b * 8 + t) * 32 + tile] = l;
    }
}

// K2: xa partials -> atomicAdd directly into g_xa. Also inits out = bo.
// grid 512 = (b * 16 + c), 64 s per chunk; block 256.
__global__ void k_xapart(const float* __restrict__ x, float* __restrict__ out,
                         const float* __restrict__ bo) {
    __shared__ float s_attn[64 * 8];       // [i][h]
    __shared__ float s_M[8], s_iL[8];
    __shared__ ull s_red[2][64][18];       // 18 KB staging (2 strips)
    int t = threadIdx.x;
    int b = blockIdx.x >> 4, c = blockIdx.x & 15;
    int w = t >> 5, lane = t & 31;

    // 512 blocks x 4 f4 covers out (8192 floats) = bo init
    if (t < 4) {
        int o = blockIdx.x * 4 + t;
        ((float4*)out)[o] = ((const float4*)bo)[o & 63];
    }

    {
        float m = g_mstat[(b * 8 + w) * 32 + lane];
        float mm = m;
#pragma unroll
        for (int o = 16; o; o >>= 1) mm = fmaxf(mm, __shfl_xor_sync(0xffffffffu, mm, o));
        float l = g_lstat[(b * 8 + w) * 32 + lane] * __expf(m - mm);
#pragma unroll
        for (int o = 16; o; o >>= 1) l += __shfl_xor_sync(0xffffffffu, l, o);
        if (lane == 0) { s_M[w] = mm; s_iL[w] = 1.0f / l; }
    }
    __syncthreads();

#pragma unroll
    for (int k = 0; k < 2; k++) {
        int idx = k * 256 + t;             // 0..511 : (h, i)
        int h = idx >> 6, i = idx & 63;
        float v = g_scores[(b * 8 + h) * 1024 + c * 64 + i];
        s_attn[i * 8 + h] = __expf(v - s_M[h]) * s_iL[h];
    }
    __syncthreads();

    int d4 = t & 63, ss = t >> 6;          // 4 strips of 16 s
    ull aclo[8], achi[8];
#pragma unroll
    for (int h = 0; h < 8; h++) { aclo[h] = 0ull; achi[h] = 0ull; }

    const float4* xb = (const float4*)(x + (size_t)(b * 1024 + c * 64 + ss * 16) * 256);
#pragma unroll 4
    for (int i = 0; i < 16; i++) {
        float4 xv = xb[i * 64 + d4];
        const float4* ap = (const float4*)(s_attn + (ss * 16 + i) * 8);
        float4 a03 = ap[0], a47 = ap[1];
        float ah[8] = {a03.x, a03.y, a03.z, a03.w, a47.x, a47.y, a47.z, a47.w};
        ull xlo = pk(xv.x, xv.y), xhi = pk(xv.z, xv.w);
#pragma unroll
        for (int h = 0; h < 8; h++) {
            ull aa = pk(ah[h], ah[h]);
            aclo[h] = ffma2(xlo, aa, aclo[h]);
            achi[h] = ffma2(xhi, aa, achi[h]);
        }
    }
    __syncthreads();
    if (ss >= 2) {
#pragma unroll
        for (int h = 0; h < 8; h++) {
            s_red[ss - 2][d4][h * 2]     = aclo[h];
            s_red[ss - 2][d4][h * 2 + 1] = achi[h];
        }
    }
    __syncthreads();
    if (ss < 2) {
#pragma unroll
        for (int h = 0; h < 8; h++) {
            aclo[h] = addf2(aclo[h], s_red[ss][d4][h * 2]);
            achi[h] = addf2(achi[h], s_red[ss][d4][h * 2 + 1]);
        }
    }
    __syncthreads();
    if (ss == 1) {
#pragma unroll
        for (int h = 0; h < 8; h++) {
            s_red[0][d4][h * 2]     = aclo[h];
            s_red[0][d4][h * 2 + 1] = achi[h];
        }
    }
    __syncthreads();
    if (ss == 0) {
#pragma unroll
        for (int h = 0; h < 8; h++) {
            float2 lo = upk(addf2(aclo[h], s_red[0][d4][h * 2]));
            float2 hi = upk(addf2(achi[h], s_red[0][d4][h * 2 + 1]));
            float* p = g_xa + (b * 8 + h) * 256 + d4 * 4;
            atomicAdd(p + 0, lo.x);
            atomicAdd(p + 1, lo.y);
            atomicAdd(p + 2, hi.x);
            atomicAdd(p + 3, hi.y);
        }
    }
}

// K3: pooled += xa-slice @ Wv-slice.  grid 256 = (jc 64) x (dq 4); block 256.
// Block handles d-range of 64; warp = d-range 8; lane = (bg 8, jg 4) -> 4b x 8j.
// Results atomicAdd into g_pooled (pre-initialized with bv in k_scores).
__global__ void k_pooled(const float* __restrict__ Wv) {
    __shared__ float s_xa[32 * 68];        // 8.5 KB (pad 68)
    __shared__ float s_wv[64 * 32];        // 8 KB   [d][32 j]
    __shared__ ull  s_red[4][16][32];      // 16 KB
    int t = threadIdx.x;
    int jc = blockIdx.x & 63, dq = blockIdx.x >> 6;
    int j0 = jc * 32, d0 = dq * 64;
    int h = jc >> 3;

    // stage xa slice [32 b][64 d]: 512 f4, 2 per thread
    const float4* xa4 = (const float4*)g_xa;
#pragma unroll
    for (int k = 0; k < 2; k++) {
        int o = k * 256 + t;               // f4 idx : (bb, d4l)
        int bb = o >> 4, d4l = o & 15;
        float4 v = xa4[(bb * 8 + h) * 64 + (d0 >> 2) + d4l];
        *(float4*)&s_xa[bb * 68 + d4l * 4] = v;
    }
    // stage Wv slice [64 d][32 j]: 512 f4, 2 per thread
#pragma unroll
    for (int k = 0; k < 2; k++) {
        int o = k * 256 + t;               // f4 idx : (dd, c4)
        int dd = o >> 3, c4 = o & 7;
        float4 w = ((const float4*)Wv)[((d0 + dd) * 2048 + j0) / 4 + c4];
        *(float4*)&s_wv[dd * 32 + c4 * 4] = w;
    }
    __syncthreads();

    int w = t >> 5, lane = t & 31;
    int bg = lane >> 2, jg = lane & 3;
    int db = w * 8;                        // warp's d-range within 64

    ull acc[4][4];
#pragma unroll
    for (int i = 0; i < 4; i++)
#pragma unroll
        for (int p = 0; p < 4; p++) acc[i][p] = 0ull;

#pragma unroll
    for (int du = 0; du < 8; du += 4) {
        int d = db + du;
        float4 xa_b[4];
#pragma unroll
        for (int i = 0; i < 4; i++)
            xa_b[i] = *(const float4*)&s_xa[(bg * 4 + i) * 68 + d];
#pragma unroll
        for (int u = 0; u < 4; u++) {
            float4 wv0 = *(const float4*)&s_wv[(d + u) * 32 + jg * 8];
            float4 wv1 = *(const float4*)&s_wv[(d + u) * 32 + jg * 8 + 4];
            ull w01 = pk(wv0.x, wv0.y), w23 = pk(wv0.z, wv0.w);
            ull w45 = pk(wv1.x, wv1.y), w67 = pk(wv1.z, wv1.w);
#pragma unroll
            for (int i = 0; i < 4; i++) {
                float xs = (&xa_b[i].x)[u];
                ull xs2 = pk(xs, xs);
                acc[i][0] = ffma2(xs2, w01, acc[i][0]);
                acc[i][1] = ffma2(xs2, w23, acc[i][1]);
                acc[i][2] = ffma2(xs2, w45, acc[i][2]);
                acc[i][3] = ffma2(xs2, w67, acc[i][3]);
            }
        }
    }

#define POOL_STORE(st) do { \
    _Pragma("unroll") for (int i = 0; i < 4; i++) \
    _Pragma("unroll") for (int p = 0; p < 4; p++) \
        s_red[st][i * 4 + p][lane] = acc[i][p]; } while (0)
#define POOL_ADD(st) do { \
    _Pragma("unroll") for (int i = 0; i < 4; i++) \
    _Pragma("unroll") for (int p = 0; p < 4; p++) \
        acc[i][p] = addf2(acc[i][p], s_red[st][i * 4 + p][lane]); } while (0)

    if (w >= 4) POOL_STORE(w - 4);
    __syncthreads();
    if (w < 4) POOL_ADD(w);
    __syncthreads();
    if (w == 2 || w == 3) POOL_STORE(w - 2);
    __syncthreads();
    if (w < 2) POOL_ADD(w);
    __syncthreads();
    if (w == 1) POOL_STORE(0);
    __syncthreads();
    if (w == 0) {
        POOL_ADD(0);
#pragma unroll
        for (int i = 0; i < 4; i++) {
            int b = bg * 4 + i;
            float* pp = g_pooled + b * 2048 + j0 + jg * 8;
#pragma unroll
            for (int p = 0; p < 4; p++) {
                float2 v = upk(acc[i][p]);
                atomicAdd(pp + p * 2 + 0, v.x);
                atomicAdd(pp + p * 2 + 1, v.y);
            }
        }
    }
#undef POOL_STORE
#undef POOL_ADD
}

// K4: out[b][e] += pooled[b, j-slice] . Wo[j-slice, e]
// grid 256 = (ec 8 x jp 32), j-slice 64; block 256. Warp = j-range 8;
// lane = (bg 8, eg 4) -> 4b x 8e; tree reduce; atomicAdd fan-in (32-way).
__global__ void k_out(const float* __restrict__ Wo, float* __restrict__ out) {
    __shared__ float s_p[32 * 68];         // [32 b][64 j] padded
    __shared__ float s_wo[64 * 32];        // [64 j][32 e]
    __shared__ ull  s_red[4][16][32];
    int t = threadIdx.x;
    int ec = blockIdx.x & 7, jp = blockIdx.x >> 3;
    int e0 = ec * 32, j0 = jp * 64;

    const float4* gp4 = (const float4*)g_pooled;
#pragma unroll
    for (int k = 0; k < 2; k++) {
        int o = k * 256 + t;               // f4 idx : (bb, j4l)
        int bb = o >> 4, j4l = o & 15;
        float4 v = gp4[bb * 512 + (j0 >> 2) + j4l];
        *(float4*)&s_p[bb * 68 + j4l * 4] = v;
    }
#pragma unroll
    for (int k = 0; k < 2; k++) {
        int o = k * 256 + t;               // f4 idx : (jj, c4)
        int jj = o >> 3, c4 = o & 7;
        float4 w4 = ((const float4*)Wo)[((j0 + jj) * 256 + e0) / 4 + c4];
        *(float4*)&s_wo[jj * 32 + c4 * 4] = w4;
    }
    __syncthreads();

    int w = t >> 5, lane = t & 31;
    int bg = lane >> 2, eg = lane & 3;
    int jj0 = w * 8;

    ull acc[4][4];
#pragma unroll
    for (int i = 0; i < 4; i++)
#pragma unroll
        for (int p = 0; p < 4; p++) acc[i][p] = 0ull;

#pragma unroll
    for (int ju = 0; ju < 8; ju += 4) {
        int j = jj0 + ju;
        float4 p_b[4];
#pragma unroll
        for (int i = 0; i < 4; i++)
            p_b[i] = *(const float4*)&s_p[(bg * 4 + i) * 68 + j];
#pragma unroll
        for (int u = 0; u < 4; u++) {
            float4 wo0 = *(const float4*)&s_wo[(j + u) * 32 + eg * 8];
            float4 wo1 = *(const float4*)&s_wo[(j + u) * 32 + eg * 8 + 4];
            ull w01 = pk(wo0.x, wo0.y), w23 = pk(wo0.z, wo0.w);
            ull w45 = pk(wo1.x, wo1.y), w67 = pk(wo1.z, wo1.w);
#pragma unroll
            for (int i = 0; i < 4; i++) {
                float ps = (&p_b[i].x)[u];
                ull ps2 = pk(ps, ps);
                acc[i][0] = ffma2(ps2, w01, acc[i][0]);
                acc[i][1] = ffma2(ps2, w23, acc[i][1]);
                acc[i][2] = ffma2(ps2, w45, acc[i][2]);
                acc[i][3] = ffma2(ps2, w67, acc[i][3]);
            }
        }
    }

#define OUT_STORE(st) do { \
    _Pragma("unroll") for (int i = 0; i < 4; i++) \
    _Pragma("unroll") for (int p = 0; p < 4; p++) \
        s_red[st][i * 4 + p][lane] = acc[i][p]; } while (0)
#define OUT_ADD(st) do { \
    _Pragma("unroll") for (int i = 0; i < 4; i++) \
    _Pragma("unroll") for (int p = 0; p < 4; p++) \
        acc[i][p] = addf2(acc[i][p], s_red[st][i * 4 + p][lane]); } while (0)

    if (w >= 4) OUT_STORE(w - 4);
    __syncthreads();
    if (w < 4) OUT_ADD(w);
    __syncthreads();
    if (w == 2 || w == 3) OUT_STORE(w - 2);
    __syncthreads();
    if (w < 2) OUT_ADD(w);
    __syncthreads();
    if (w == 1) OUT_STORE(0);
    __syncthreads();
    if (w == 0) {
        OUT_ADD(0);
#pragma unroll
        for (int i = 0; i < 4; i++) {
            int b = bg * 4 + i;
            float* op = out + b * 256 + e0 + eg * 8;
#pragma unroll
            for (int p = 0; p < 4; p++) {
                float2 v = upk(acc[i][p]);
                atomicAdd(op + p * 2 + 0, v.x);
                atomicAdd(op + p * 2 + 1, v.y);
            }
        }
    }
#undef OUT_STORE
#undef OUT_ADD
}

extern "C" void kernel_launch(void* const* d_in, const int* in_sizes, int n_in,
                              void* d_out, int out_size) {
    const float* x     = (const float*)d_in[0];
    const float* Wk    = (const float*)d_in[1];
    // d_in[2] = bk: constant shift per (b,h) across s -> softmax-invariant, unused
    const float* Wv    = (const float*)d_in[3];
    const float* bv    = (const float*)d_in[4];
    const float* query = (const float*)d_in[5];
    const float* Wo    = (const float*)d_in[6];
    const float* bo    = (const float*)d_in[7];
    float* out = (float*)d_out;

    k_wq<<<256, 256>>>(Wk, query);
    k_scores<<<1024, 256>>>(x, bv);      // also zeroes g_xa, inits g_pooled=bv
    k_xapart<<<512, 256>>>(x, out, bo);  // atomic xa accumulate, inits out=bo
    k_pooled<<<256, 256>>>(Wv);          // atomic accumulate into g_pooled
    k_out<<<256, 256>>>(Wo, out);        // atomic accumulate into out
}

// round 9
// speedup vs baseline: 1.5978x; 1.5978x over previous
#include <cuda_runtime.h>

typedef unsigned long long ull;

// Problem constants
#define DN 256
#define HN 8
#define BN 32
#define SN 1024
#define NTILE 32   // s-tiles of 32 for scores / softmax stats

// Scratch (device globals; no allocation allowed)
__device__ float g_wq[HN * DN];                 // [h][d] effective query weights
__device__ float g_scores[BN * HN * SN];        // [b][h][s] raw scores
__device__ float g_mstat[BN * HN * NTILE];      // per-tile max
__device__ float g_lstat[BN * HN * NTILE];      // per-tile sum of exp(v - m_tile)
__device__ float g_xa[BN * HN * DN];            // [b][h][d] xa (atomic-accumulated)
__device__ float g_pooled[BN * HN * DN];        // [b][j], j = h*256+d

__device__ __forceinline__ float dot4(float4 a, float4 b) {
    return a.x * b.x + a.y * b.y + a.z * b.z + a.w * b.w;
}
// sm_103a packed fp32x2 FMA (2 FMA per instruction)
__device__ __forceinline__ ull ffma2(ull a, ull b, ull c) {
    ull d;
    asm("fma.rn.f32x2 %0, %1, %2, %3;" : "=l"(d) : "l"(a), "l"(b), "l"(c));
    return d;
}
__device__ __forceinline__ ull pk(float lo, float hi) {
    ull r;
    asm("mov.b64 %0, {%1, %2};" : "=l"(r) : "f"(lo), "f"(hi));
    return r;
}
__device__ __forceinline__ float2 upk(ull v) {
    float2 r;
    asm("mov.b64 {%0, %1}, %2;" : "=f"(r.x), "=f"(r.y) : "l"(v));
    return r;
}
__device__ __forceinline__ ull addf2(ull a, ull b) {
    ull d;
    asm("add.rn.f32x2 %0, %1, %2;" : "=l"(d) : "l"(a), "l"(b));
    return d;
}

// K0: Wq_eff[h][d] = sum_{d'} Wk[d][h*256+d'] * query[h][d']   (one warp per output)
__global__ void k_wq(const float* __restrict__ Wk, const float* __restrict__ query) {
    int wid = blockIdx.x * 8 + (threadIdx.x >> 5);
    int lane = threadIdx.x & 31;
    int d = wid >> 3, h = wid & 7;
    const float4* wk4 = (const float4*)(Wk + d * 2048 + h * 256);
    const float4* q4  = (const float4*)(query + h * 256);
    float v = dot4(wk4[lane], q4[lane]) + dot4(wk4[lane + 32], q4[lane + 32]);
#pragma unroll
    for (int o = 16; o; o >>= 1) v += __shfl_xor_sync(0xffffffffu, v, o);
    if (lane == 0) g_wq[h * 256 + d] = v;
}

// K1: scores + per-tile softmax stats. x streamed straight into registers
// (coalesced, issued FIRST to overlap the wq staging chain), wq from smem
// broadcast, butterfly reduce over the 8 d-segment lanes. Zeroes g_xa.
// grid 1024 = (b * 32 + tile); block 256; thread = (s 32, dseg 8).
__global__ void k_scores(const float* __restrict__ x) {
    __shared__ float s_wq[2048];
    __shared__ float s_sc[32 * 9];
    int t = threadIdx.x;
    int b = blockIdx.x >> 5, tile = blockIdx.x & 31;
    int s = t >> 3, dseg = t & 7;

    // x loads first: 8 independent coalesced f4 LDGs in flight
    const float4* xr = (const float4*)(x + (size_t)(b * 1024 + tile * 32 + s) * 256);
    float4 xv[8];
#pragma unroll
    for (int k = 0; k < 8; k++) xv[k] = xr[k * 8 + dseg];

    // zero g_xa: 1024 blocks x 16 f4 = all of g_xa
    if (t < 16)
        ((float4*)g_xa)[blockIdx.x * 16 + t] = make_float4(0.f, 0.f, 0.f, 0.f);

#pragma unroll
    for (int k = 0; k < 8; k++) s_wq[k * 256 + t] = g_wq[k * 256 + t];
    __syncthreads();

    float acc[8];
#pragma unroll
    for (int h = 0; h < 8; h++) {
        const float4* wr = (const float4*)(s_wq + h * 256);
        ull a0 = 0ull, a1 = 0ull;
#pragma unroll
        for (int k = 0; k < 8; k++) {
            float4 wv = wr[k * 8 + dseg];
            a0 = ffma2(pk(xv[k].x, xv[k].y), pk(wv.x, wv.y), a0);
            a1 = ffma2(pk(xv[k].z, xv[k].w), pk(wv.z, wv.w), a1);
        }
        float2 f0 = upk(a0), f1 = upk(a1);
        acc[h] = (f0.x + f0.y) + (f1.x + f1.y);
    }
    // butterfly over the 8 dseg lanes (strides 1,2,4)
#pragma unroll
    for (int o = 1; o < 8; o <<= 1)
#pragma unroll
        for (int h = 0; h < 8; h++)
            acc[h] += __shfl_xor_sync(0xffffffffu, acc[h], o);
    float v = acc[0];
#pragma unroll
    for (int h = 1; h < 8; h++) v = (dseg == h) ? acc[h] : v;

    g_scores[(b * 8 + dseg) * 1024 + tile * 32 + s] = v;
    s_sc[s * 9 + dseg] = v;
    __syncthreads();

    if (t < 8) {
        float m = -1e30f;
#pragma unroll
        for (int i = 0; i < 32; i++) m = fmaxf(m, s_sc[i * 9 + t]);
        float l = 0.f;
#pragma unroll
        for (int i = 0; i < 32; i++) l += __expf(s_sc[i * 9 + t] - m);
        g_mstat[(b * 8 + t) * 32 + tile] = m;
        g_lstat[(b * 8 + t) * 32 + tile] = l;
    }
}

// K2: xa partials -> atomicAdd directly into g_xa.
// grid 512 = (b * 16 + c), 64 s per chunk; block 256.
__global__ void k_xapart(const float* __restrict__ x) {
    __shared__ float s_attn[64 * 8];       // [i][h]
    __shared__ float s_M[8], s_iL[8];
    __shared__ ull s_red[2][64][18];       // 18 KB staging (2 strips)
    int t = threadIdx.x;
    int b = blockIdx.x >> 4, c = blockIdx.x & 15;
    int w = t >> 5, lane = t & 31;

    {
        float m = g_mstat[(b * 8 + w) * 32 + lane];
        float mm = m;
#pragma unroll
        for (int o = 16; o; o >>= 1) mm = fmaxf(mm, __shfl_xor_sync(0xffffffffu, mm, o));
        float l = g_lstat[(b * 8 + w) * 32 + lane] * __expf(m - mm);
#pragma unroll
        for (int o = 16; o; o >>= 1) l += __shfl_xor_sync(0xffffffffu, l, o);
        if (lane == 0) { s_M[w] = mm; s_iL[w] = 1.0f / l; }
    }
    __syncthreads();

#pragma unroll
    for (int k = 0; k < 2; k++) {
        int idx = k * 256 + t;             // 0..511 : (h, i)
        int h = idx >> 6, i = idx & 63;
        float v = g_scores[(b * 8 + h) * 1024 + c * 64 + i];
        s_attn[i * 8 + h] = __expf(v - s_M[h]) * s_iL[h];
    }
    __syncthreads();

    int d4 = t & 63, ss = t >> 6;          // 4 strips of 16 s
    ull aclo[8], achi[8];
#pragma unroll
    for (int h = 0; h < 8; h++) { aclo[h] = 0ull; achi[h] = 0ull; }

    const float4* xb = (const float4*)(x + (size_t)(b * 1024 + c * 64 + ss * 16) * 256);
#pragma unroll 8
    for (int i = 0; i < 16; i++) {
        float4 xv = xb[i * 64 + d4];
        const float4* ap = (const float4*)(s_attn + (ss * 16 + i) * 8);
        float4 a03 = ap[0], a47 = ap[1];
        float ah[8] = {a03.x, a03.y, a03.z, a03.w, a47.x, a47.y, a47.z, a47.w};
        ull xlo = pk(xv.x, xv.y), xhi = pk(xv.z, xv.w);
#pragma unroll
        for (int h = 0; h < 8; h++) {
            ull aa = pk(ah[h], ah[h]);
            aclo[h] = ffma2(xlo, aa, aclo[h]);
            achi[h] = ffma2(xhi, aa, achi[h]);
        }
    }
    __syncthreads();
    if (ss >= 2) {
#pragma unroll
        for (int h = 0; h < 8; h++) {
            s_red[ss - 2][d4][h * 2]     = aclo[h];
            s_red[ss - 2][d4][h * 2 + 1] = achi[h];
        }
    }
    __syncthreads();
    if (ss < 2) {
#pragma unroll
        for (int h = 0; h < 8; h++) {
            aclo[h] = addf2(aclo[h], s_red[ss][d4][h * 2]);
            achi[h] = addf2(achi[h], s_red[ss][d4][h * 2 + 1]);
        }
    }
    __syncthreads();
    if (ss == 1) {
#pragma unroll
        for (int h = 0; h < 8; h++) {
            s_red[0][d4][h * 2]     = aclo[h];
            s_red[0][d4][h * 2 + 1] = achi[h];
        }
    }
    __syncthreads();
    if (ss == 0) {
#pragma unroll
        for (int h = 0; h < 8; h++) {
            float2 lo = upk(addf2(aclo[h], s_red[0][d4][h * 2]));
            float2 hi = upk(addf2(achi[h], s_red[0][d4][h * 2 + 1]));
            float* p = g_xa + (b * 8 + h) * 256 + d4 * 4;
            atomicAdd(p + 0, lo.x);
            atomicAdd(p + 1, lo.y);
            atomicAdd(p + 2, hi.x);
            atomicAdd(p + 3, hi.y);
        }
    }
}

// K3: pooled = xa @ Wv + bv.  grid 64 (j-chunks of 32, h = jc>>3); block 256.
// Register-blocked: warp = d-range of 32 (8-way d-split), lane = (bg 8, jg 4)
// -> 4 b x 8 j per thread, f32x2 FMAs, staged tree reduction over warps.
// Also inits out = bo (blocks 0..31 cover all 8192 outputs).
__global__ void k_pooled(const float* __restrict__ Wv, const float* __restrict__ bv,
                         float* __restrict__ out, const float* __restrict__ bo) {
    __shared__ float s_xa[32 * 260];       // 33 KB (padded rows)
    __shared__ float s_wv[256 * 32];       // 32 KB  [d][32 j]
    __shared__ ull  s_red[4][16][32];      // 16 KB  [stage][slot][lane]
    int t = threadIdx.x;
    int jc = blockIdx.x;                   // 0..63
    int j0 = jc * 32;
    int h = jc >> 3;

    // stage xa for this head: 2048 f4, 8 per thread
    const float4* xa4 = (const float4*)g_xa;
#pragma unroll
    for (int k = 0; k < 8; k++) {
        int o = k * 256 + t;               // f4 idx : (bb, d4)
        int bb = o >> 6, d4 = o & 63;
        float4 v = xa4[(bb * 8 + h) * 64 + d4];
        *(float4*)&s_xa[bb * 260 + d4 * 4] = v;
    }
    // stage Wv tile [256 d][32 j]
#pragma unroll
    for (int k = 0; k < 8; k++) {
        int o = k * 256 + t;               // f4 idx : (d, c4)
        int d = o >> 3, c4 = o & 7;
        float4 w = ((const float4*)Wv)[(d * 2048 + j0) / 4 + c4];
        *(float4*)&s_wv[d * 32 + c4 * 4] = w;
    }
    int gid = jc * 256 + t;
    if (gid < 8192) out[gid] = bo[gid & 255];
    __syncthreads();

    int w = t >> 5, lane = t & 31;
    int bg = lane >> 2, jg = lane & 3;     // 4 b rows, 8 j cols per thread
    int d0 = w * 32;

    ull acc[4][4];                         // [b][j-pair]
#pragma unroll
    for (int i = 0; i < 4; i++)
#pragma unroll
        for (int p = 0; p < 4; p++) acc[i][p] = 0ull;

#pragma unroll
    for (int du = 0; du < 32; du += 4) {
        int d = d0 + du;
        float4 xa_b[4];
#pragma unroll
        for (int i = 0; i < 4; i++)
            xa_b[i] = *(const float4*)&s_xa[(bg * 4 + i) * 260 + d];
#pragma unroll
        for (int u = 0; u < 4; u++) {
            float4 wv0 = *(const float4*)&s_wv[(d + u) * 32 + jg * 8];
            float4 wv1 = *(const float4*)&s_wv[(d + u) * 32 + jg * 8 + 4];
            ull w01 = pk(wv0.x, wv0.y), w23 = pk(wv0.z, wv0.w);
            ull w45 = pk(wv1.x, wv1.y), w67 = pk(wv1.z, wv1.w);
#pragma unroll
            for (int i = 0; i < 4; i++) {
                float xs = (&xa_b[i].x)[u];
                ull xs2 = pk(xs, xs);
                acc[i][0] = ffma2(xs2, w01, acc[i][0]);
                acc[i][1] = ffma2(xs2, w23, acc[i][1]);
                acc[i][2] = ffma2(xs2, w45, acc[i][2]);
                acc[i][3] = ffma2(xs2, w67, acc[i][3]);
            }
        }
    }

    // tree reduce over the 8 d-split warps
#define POOL_STORE(st) do { \
    _Pragma("unroll") for (int i = 0; i < 4; i++) \
    _Pragma("unroll") for (int p = 0; p < 4; p++) \
        s_red[st][i * 4 + p][lane] = acc[i][p]; } while (0)
#define POOL_ADD(st) do { \
    _Pragma("unroll") for (int i = 0; i < 4; i++) \
    _Pragma("unroll") for (int p = 0; p < 4; p++) \
        acc[i][p] = addf2(acc[i][p], s_red[st][i * 4 + p][lane]); } while (0)

    if (w >= 4) POOL_STORE(w - 4);
    __syncthreads();
    if (w < 4) POOL_ADD(w);
    __syncthreads();
    if (w == 2 || w == 3) POOL_STORE(w - 2);
    __syncthreads();
    if (w < 2) POOL_ADD(w);
    __syncthreads();
    if (w == 1) POOL_STORE(0);
    __syncthreads();
    if (w == 0) {
        POOL_ADD(0);
#pragma unroll
        for (int i = 0; i < 4; i++) {
            int b = bg * 4 + i;
#pragma unroll
            for (int p = 0; p < 2; p++) {
                float2 lo = upk(acc[i][p * 2]);
                float2 hi = upk(acc[i][p * 2 + 1]);
                float4 bvv = ((const float4*)bv)[(j0 >> 2) + jg * 2 + p];
                float4 o4 = make_float4(lo.x + bvv.x, lo.y + bvv.y,
                                        hi.x + bvv.z, hi.y + bvv.w);
                ((float4*)g_pooled)[b * 512 + (j0 >> 2) + jg * 2 + p] = o4;
            }
        }
    }
#undef POOL_STORE
#undef POOL_ADD
}

// K4: out[b][e] += pooled[b, j-slice] . Wo[j-slice, e]
// grid 128 = (ec 8 x jp 16); block 256. Register-blocked: warp = j-range 16,
// lane = (bg 8, eg 4) -> 4 b x 8 e per thread; tree reduce; atomicAdd fan-in.
__global__ void k_out(const float* __restrict__ Wo, float* __restrict__ out) {
    __shared__ float s_p[32 * 132];        // [32 b][128 j] padded
    __shared__ float s_wo[128 * 32];       // [128 j][32 e]
    __shared__ ull  s_red[4][16][32];
    int t = threadIdx.x;
    int ec = blockIdx.x & 7, jp = blockIdx.x >> 3;
    int e0 = ec * 32, j0 = jp * 128;

    const float4* gp4 = (const float4*)g_pooled;
#pragma unroll
    for (int k = 0; k < 4; k++) {
        int o = k * 256 + t;               // f4 idx : (bb, j4)
        int bb = o >> 5, j4 = o & 31;
        float4 v = gp4[bb * 512 + (j0 >> 2) + j4];
        *(float4*)&s_p[bb * 132 + j4 * 4] = v;
    }
#pragma unroll
    for (int k = 0; k < 4; k++) {
        int o = k * 256 + t;               // f4 idx : (jj, c4)
        int jj = o >> 3, c4 = o & 7;
        float4 w4 = ((const float4*)Wo)[((j0 + jj) * 256 + e0) / 4 + c4];
        *(float4*)&s_wo[jj * 32 + c4 * 4] = w4;
    }
    __syncthreads();

    int w = t >> 5, lane = t & 31;
    int bg = lane >> 2, eg = lane & 3;
    int jj0 = w * 16;

    ull acc[4][4];
#pragma unroll
    for (int i = 0; i < 4; i++)
#pragma unroll
        for (int p = 0; p < 4; p++) acc[i][p] = 0ull;

#pragma unroll
    for (int ju = 0; ju < 16; ju += 4) {
        int j = jj0 + ju;
        float4 p_b[4];
#pragma unroll
        for (int i = 0; i < 4; i++)
            p_b[i] = *(const float4*)&s_p[(bg * 4 + i) * 132 + j];
#pragma unroll
        for (int u = 0; u < 4; u++) {
            float4 wo0 = *(const float4*)&s_wo[(j + u) * 32 + eg * 8];
            float4 wo1 = *(const float4*)&s_wo[(j + u) * 32 + eg * 8 + 4];
            ull w01 = pk(wo0.x, wo0.y), w23 = pk(wo0.z, wo0.w);
            ull w45 = pk(wo1.x, wo1.y), w67 = pk(wo1.z, wo1.w);
#pragma unroll
            for (int i = 0; i < 4; i++) {
                float ps = (&p_b[i].x)[u];
                ull ps2 = pk(ps, ps);
                acc[i][0] = ffma2(ps2, w01, acc[i][0]);
                acc[i][1] = ffma2(ps2, w23, acc[i][1]);
                acc[i][2] = ffma2(ps2, w45, acc[i][2]);
                acc[i][3] = ffma2(ps2, w67, acc[i][3]);
            }
        }
    }

#define OUT_STORE(st) do { \
    _Pragma("unroll") for (int i = 0; i < 4; i++) \
    _Pragma("unroll") for (int p = 0; p < 4; p++) \
        s_red[st][i * 4 + p][lane] = acc[i][p]; } while (0)
#define OUT_ADD(st) do { \
    _Pragma("unroll") for (int i = 0; i < 4; i++) \
    _Pragma("unroll") for (int p = 0; p < 4; p++) \
        acc[i][p] = addf2(acc[i][p], s_red[st][i * 4 + p][lane]); } while (0)

    if (w >= 4) OUT_STORE(w - 4);
    __syncthreads();
    if (w < 4) OUT_ADD(w);
    __syncthreads();
    if (w == 2 || w == 3) OUT_STORE(w - 2);
    __syncthreads();
    if (w < 2) OUT_ADD(w);
    __syncthreads();
    if (w == 1) OUT_STORE(0);
    __syncthreads();
    if (w == 0) {
        OUT_ADD(0);
#pragma unroll
        for (int i = 0; i < 4; i++) {
            int b = bg * 4 + i;
            float* op = out + b * 256 + e0 + eg * 8;
#pragma unroll
            for (int p = 0; p < 4; p++) {
                float2 v = upk(acc[i][p]);
                atomicAdd(op + p * 2 + 0, v.x);
                atomicAdd(op + p * 2 + 1, v.y);
            }
        }
    }
#undef OUT_STORE
#undef OUT_ADD
}

extern "C" void kernel_launch(void* const* d_in, const int* in_sizes, int n_in,
                              void* d_out, int out_size) {
    const float* x     = (const float*)d_in[0];
    const float* Wk    = (const float*)d_in[1];
    // d_in[2] = bk: constant shift per (b,h) across s -> softmax-invariant, unused
    const float* Wv    = (const float*)d_in[3];
    const float* bv    = (const float*)d_in[4];
    const float* query = (const float*)d_in[5];
    const float* Wo    = (const float*)d_in[6];
    const float* bo    = (const float*)d_in[7];
    float* out = (float*)d_out;

    k_wq<<<256, 256>>>(Wk, query);
    k_scores<<<1024, 256>>>(x);      // also zeroes g_xa
    k_xapart<<<512, 256>>>(x);       // atomic-accumulates into g_xa
    k_pooled<<<64, 256>>>(Wv, bv, out, bo);
    k_out<<<128, 256>>>(Wo, out);
}

// round 10
// speedup vs baseline: 1.6282x; 1.0191x over previous
#include <cuda_runtime.h>

typedef unsigned long long ull;

// Problem constants
#define DN 256
#define HN 8
#define BN 32
#define SN 1024
#define NTILE 32   // s-tiles of 32 for scores / softmax stats

// Scratch (device globals; no allocation allowed)
__device__ float g_wq[HN * DN];                 // [h][d] effective query weights
__device__ float g_scores[BN * HN * SN];        // [b][h][s] raw scores
__device__ float g_mstat[BN * HN * NTILE];      // per-tile max
__device__ float g_lstat[BN * HN * NTILE];      // per-tile sum of exp(v - m_tile)
__device__ float g_xa[BN * HN * DN];            // [b][h][d] xa (atomic-accumulated)
__device__ float g_pooled[BN * HN * DN];        // [b][j], j = h*256+d

__device__ __forceinline__ float dot4(float4 a, float4 b) {
    return a.x * b.x + a.y * b.y + a.z * b.z + a.w * b.w;
}
// sm_103a packed fp32x2 FMA (2 FMA per instruction)
__device__ __forceinline__ ull ffma2(ull a, ull b, ull c) {
    ull d;
    asm("fma.rn.f32x2 %0, %1, %2, %3;" : "=l"(d) : "l"(a), "l"(b), "l"(c));
    return d;
}
__device__ __forceinline__ ull pk(float lo, float hi) {
    ull r;
    asm("mov.b64 %0, {%1, %2};" : "=l"(r) : "f"(lo), "f"(hi));
    return r;
}
__device__ __forceinline__ float2 upk(ull v) {
    float2 r;
    asm("mov.b64 {%0, %1}, %2;" : "=f"(r.x), "=f"(r.y) : "l"(v));
    return r;
}
__device__ __forceinline__ ull addf2(ull a, ull b) {
    ull d;
    asm("add.rn.f32x2 %0, %1, %2;" : "=l"(d) : "l"(a), "l"(b));
    return d;
}

// K0: Wq_eff[h][d] = sum_{d'} Wk[d][h*256+d'] * query[h][d']   (one warp per output)
__global__ void k_wq(const float* __restrict__ Wk, const float* __restrict__ query) {
    int wid = blockIdx.x * 8 + (threadIdx.x >> 5);
    int lane = threadIdx.x & 31;
    int d = wid >> 3, h = wid & 7;
    const float4* wk4 = (const float4*)(Wk + d * 2048 + h * 256);
    const float4* q4  = (const float4*)(query + h * 256);
    float v = dot4(wk4[lane], q4[lane]) + dot4(wk4[lane + 32], q4[lane + 32]);
#pragma unroll
    for (int o = 16; o; o >>= 1) v += __shfl_xor_sync(0xffffffffu, v, o);
    if (lane == 0) g_wq[h * 256 + d] = v;
}

// K1: scores + per-tile softmax stats. x streamed straight into registers
// (coalesced, issued FIRST to overlap the wq staging chain), wq from smem
// broadcast, butterfly reduce over the 8 d-segment lanes. Zeroes g_xa.
// grid 1024 = (b * 32 + tile); block 256; thread = (s 32, dseg 8).
__global__ void k_scores(const float* __restrict__ x) {
    __shared__ float s_wq[2048];
    __shared__ float s_sc[32 * 9];
    int t = threadIdx.x;
    int b = blockIdx.x >> 5, tile = blockIdx.x & 31;
    int s = t >> 3, dseg = t & 7;

    // x loads first: 8 independent coalesced f4 LDGs in flight
    const float4* xr = (const float4*)(x + (size_t)(b * 1024 + tile * 32 + s) * 256);
    float4 xv[8];
#pragma unroll
    for (int k = 0; k < 8; k++) xv[k] = xr[k * 8 + dseg];

    // zero g_xa: 1024 blocks x 16 f4 = all of g_xa
    if (t < 16)
        ((float4*)g_xa)[blockIdx.x * 16 + t] = make_float4(0.f, 0.f, 0.f, 0.f);

#pragma unroll
    for (int k = 0; k < 8; k++) s_wq[k * 256 + t] = g_wq[k * 256 + t];
    __syncthreads();

    float acc[8];
#pragma unroll
    for (int h = 0; h < 8; h++) {
        const float4* wr = (const float4*)(s_wq + h * 256);
        ull a0 = 0ull, a1 = 0ull;
#pragma unroll
        for (int k = 0; k < 8; k++) {
            float4 wv = wr[k * 8 + dseg];
            a0 = ffma2(pk(xv[k].x, xv[k].y), pk(wv.x, wv.y), a0);
            a1 = ffma2(pk(xv[k].z, xv[k].w), pk(wv.z, wv.w), a1);
        }
        float2 f0 = upk(a0), f1 = upk(a1);
        acc[h] = (f0.x + f0.y) + (f1.x + f1.y);
    }
    // butterfly over the 8 dseg lanes (strides 1,2,4)
#pragma unroll
    for (int o = 1; o < 8; o <<= 1)
#pragma unroll
        for (int h = 0; h < 8; h++)
            acc[h] += __shfl_xor_sync(0xffffffffu, acc[h], o);
    float v = acc[0];
#pragma unroll
    for (int h = 1; h < 8; h++) v = (dseg == h) ? acc[h] : v;

    g_scores[(b * 8 + dseg) * 1024 + tile * 32 + s] = v;
    s_sc[s * 9 + dseg] = v;
    __syncthreads();

    if (t < 8) {
        float m = -1e30f;
#pragma unroll
        for (int i = 0; i < 32; i++) m = fmaxf(m, s_sc[i * 9 + t]);
        float l = 0.f;
#pragma unroll
        for (int i = 0; i < 32; i++) l += __expf(s_sc[i * 9 + t] - m);
        g_mstat[(b * 8 + t) * 32 + tile] = m;
        g_lstat[(b * 8 + t) * 32 + tile] = l;
    }
}

// K2: xa partials -> atomicAdd directly into g_xa.
// grid 512 = (b * 16 + c), 64 s per chunk; block 256.
__global__ void k_xapart(const float* __restrict__ x) {
    __shared__ float s_attn[64 * 8];       // [i][h]
    __shared__ float s_M[8], s_iL[8];
    __shared__ ull s_red[2][64][18];       // 18 KB staging (2 strips)
    int t = threadIdx.x;
    int b = blockIdx.x >> 4, c = blockIdx.x & 15;
    int w = t >> 5, lane = t & 31;

    {
        float m = g_mstat[(b * 8 + w) * 32 + lane];
        float mm = m;
#pragma unroll
        for (int o = 16; o; o >>= 1) mm = fmaxf(mm, __shfl_xor_sync(0xffffffffu, mm, o));
        float l = g_lstat[(b * 8 + w) * 32 + lane] * __expf(m - mm);
#pragma unroll
        for (int o = 16; o; o >>= 1) l += __shfl_xor_sync(0xffffffffu, l, o);
        if (lane == 0) { s_M[w] = mm; s_iL[w] = 1.0f / l; }
    }
    __syncthreads();

#pragma unroll
    for (int k = 0; k < 2; k++) {
        int idx = k * 256 + t;             // 0..511 : (h, i)
        int h = idx >> 6, i = idx & 63;
        float v = g_scores[(b * 8 + h) * 1024 + c * 64 + i];
        s_attn[i * 8 + h] = __expf(v - s_M[h]) * s_iL[h];
    }
    __syncthreads();

    int d4 = t & 63, ss = t >> 6;          // 4 strips of 16 s
    ull aclo[8], achi[8];
#pragma unroll
    for (int h = 0; h < 8; h++) { aclo[h] = 0ull; achi[h] = 0ull; }

    const float4* xb = (const float4*)(x + (size_t)(b * 1024 + c * 64 + ss * 16) * 256);
#pragma unroll 8
    for (int i = 0; i < 16; i++) {
        float4 xv = xb[i * 64 + d4];
        const float4* ap = (const float4*)(s_attn + (ss * 16 + i) * 8);
        float4 a03 = ap[0], a47 = ap[1];
        float ah[8] = {a03.x, a03.y, a03.z, a03.w, a47.x, a47.y, a47.z, a47.w};
        ull xlo = pk(xv.x, xv.y), xhi = pk(xv.z, xv.w);
#pragma unroll
        for (int h = 0; h < 8; h++) {
            ull aa = pk(ah[h], ah[h]);
            aclo[h] = ffma2(xlo, aa, aclo[h]);
            achi[h] = ffma2(xhi, aa, achi[h]);
        }
    }
    __syncthreads();
    if (ss >= 2) {
#pragma unroll
        for (int h = 0; h < 8; h++) {
            s_red[ss - 2][d4][h * 2]     = aclo[h];
            s_red[ss - 2][d4][h * 2 + 1] = achi[h];
        }
    }
    __syncthreads();
    if (ss < 2) {
#pragma unroll
        for (int h = 0; h < 8; h++) {
            aclo[h] = addf2(aclo[h], s_red[ss][d4][h * 2]);
            achi[h] = addf2(achi[h], s_red[ss][d4][h * 2 + 1]);
        }
    }
    __syncthreads();
    if (ss == 1) {
#pragma unroll
        for (int h = 0; h < 8; h++) {
            s_red[0][d4][h * 2]     = aclo[h];
            s_red[0][d4][h * 2 + 1] = achi[h];
        }
    }
    __syncthreads();
    if (ss == 0) {
#pragma unroll
        for (int h = 0; h < 8; h++) {
            float2 lo = upk(addf2(aclo[h], s_red[0][d4][h * 2]));
            float2 hi = upk(addf2(achi[h], s_red[0][d4][h * 2 + 1]));
            float* p = g_xa + (b * 8 + h) * 256 + d4 * 4;
            atomicAdd(p + 0, lo.x);
            atomicAdd(p + 1, lo.y);
            atomicAdd(p + 2, hi.x);
            atomicAdd(p + 3, hi.y);
        }
    }
}

// K3: pooled = xa @ Wv + bv.  grid 256 = (jc 0..127: j-chunks of 16) x (bh 0..1:
// b-halves of 16). Output-disjoint split: full d=256 reduction stays in-block
// (8 d-split warps + tree reduce), NO atomics. ~37KB smem -> multi-block/SM.
// lane = (bg 8, jg 4) -> 2 b x 4 j per thread. Also inits out = bo.
__global__ void k_pooled(const float* __restrict__ Wv, const float* __restrict__ bv,
                         float* __restrict__ out, const float* __restrict__ bo) {
    __shared__ float s_xa[16 * 260];       // 16.6 KB (padded rows)
    __shared__ float s_wv[256 * 16];       // 16 KB  [d][16 j]
    __shared__ ull  s_red[4][4][32];       // 4 KB   [stage][slot][lane]
    int t = threadIdx.x;
    int jc = blockIdx.x & 127, bh = blockIdx.x >> 7;
    int j0 = jc * 16, b0 = bh * 16;
    int h = jc >> 4;

    // stage xa half [16 b][256 d]: 1024 f4, 4 per thread
    const float4* xa4 = (const float4*)g_xa;
#pragma unroll
    for (int k = 0; k < 4; k++) {
        int o = k * 256 + t;               // f4 idx : (bb, d4)
        int bb = o >> 6, d4 = o & 63;
        float4 v = xa4[((b0 + bb) * 8 + h) * 64 + d4];
        *(float4*)&s_xa[bb * 260 + d4 * 4] = v;
    }
    // stage Wv tile [256 d][16 j]: 1024 f4, 4 per thread
#pragma unroll
    for (int k = 0; k < 4; k++) {
        int o = k * 256 + t;               // f4 idx : (d, c4)
        int d = o >> 2, c4 = o & 3;
        float4 w = ((const float4*)Wv)[(d * 2048 + j0) / 4 + c4];
        *(float4*)&s_wv[d * 16 + c4 * 4] = w;
    }
    // init out = bo: 256 blocks x 8 f4 = 8192 floats
    if (t < 8) {
        int o = blockIdx.x * 8 + t;
        ((float4*)out)[o] = ((const float4*)bo)[o & 63];
    }
    __syncthreads();

    int w = t >> 5, lane = t & 31;
    int bg = lane >> 2, jg = lane & 3;     // 2 b rows, 4 j cols per thread
    int d0 = w * 32;

    ull acc[2][2];                         // [b][j-pair]
#pragma unroll
    for (int i = 0; i < 2; i++)
#pragma unroll
        for (int p = 0; p < 2; p++) acc[i][p] = 0ull;

#pragma unroll
    for (int du = 0; du < 32; du += 4) {
        int d = d0 + du;
        float4 xa_b[2];
#pragma unroll
        for (int i = 0; i < 2; i++)
            xa_b[i] = *(const float4*)&s_xa[(bg * 2 + i) * 260 + d];
#pragma unroll
        for (int u = 0; u < 4; u++) {
            float4 wv0 = *(const float4*)&s_wv[(d + u) * 16 + jg * 4];
            ull w01 = pk(wv0.x, wv0.y), w23 = pk(wv0.z, wv0.w);
#pragma unroll
            for (int i = 0; i < 2; i++) {
                float xs = (&xa_b[i].x)[u];
                ull xs2 = pk(xs, xs);
                acc[i][0] = ffma2(xs2, w01, acc[i][0]);
                acc[i][1] = ffma2(xs2, w23, acc[i][1]);
            }
        }
    }

    // tree reduce over the 8 d-split warps
#define POOL_STORE(st) do { \
    _Pragma("unroll") for (int i = 0; i < 2; i++) \
    _Pragma("unroll") for (int p = 0; p < 2; p++) \
        s_red[st][i * 2 + p][lane] = acc[i][p]; } while (0)
#define POOL_ADD(st) do { \
    _Pragma("unroll") for (int i = 0; i < 2; i++) \
    _Pragma("unroll") for (int p = 0; p < 2; p++) \
        acc[i][p] = addf2(acc[i][p], s_red[st][i * 2 + p][lane]); } while (0)

    if (w >= 4) POOL_STORE(w - 4);
    __syncthreads();
    if (w < 4) POOL_ADD(w);
    __syncthreads();
    if (w == 2 || w == 3) POOL_STORE(w - 2);
    __syncthreads();
    if (w < 2) POOL_ADD(w);
    __syncthreads();
    if (w == 1) POOL_STORE(0);
    __syncthreads();
    if (w == 0) {
        POOL_ADD(0);
#pragma unroll
        for (int i = 0; i < 2; i++) {
            int b = b0 + bg * 2 + i;
            float2 lo = upk(acc[i][0]);
            float2 hi = upk(acc[i][1]);
            float4 bvv = ((const float4*)bv)[(j0 >> 2) + jg];
            float4 o4 = make_float4(lo.x + bvv.x, lo.y + bvv.y,
                                    hi.x + bvv.z, hi.y + bvv.w);
            ((float4*)g_pooled)[b * 512 + (j0 >> 2) + jg] = o4;
        }
    }
#undef POOL_STORE
#undef POOL_ADD
}

// K4: out[b][e] += pooled[b, j-slice] . Wo[j-slice, e]
// grid 128 = (ec 8 x jp 16); block 256. Register-blocked: warp = j-range 16,
// lane = (bg 8, eg 4) -> 4 b x 8 e per thread; tree reduce; atomicAdd fan-in.
__global__ void k_out(const float* __restrict__ Wo, float* __restrict__ out) {
    __shared__ float s_p[32 * 132];        // [32 b][128 j] padded
    __shared__ float s_wo[128 * 32];       // [128 j][32 e]
    __shared__ ull  s_red[4][16][32];
    int t = threadIdx.x;
    int ec = blockIdx.x & 7, jp = blockIdx.x >> 3;
    int e0 = ec * 32, j0 = jp * 128;

    const float4* gp4 = (const float4*)g_pooled;
#pragma unroll
    for (int k = 0; k < 4; k++) {
        int o = k * 256 + t;               // f4 idx : (bb, j4)
        int bb = o >> 5, j4 = o & 31;
        float4 v = gp4[bb * 512 + (j0 >> 2) + j4];
        *(float4*)&s_p[bb * 132 + j4 * 4] = v;
    }
#pragma unroll
    for (int k = 0; k < 4; k++) {
        int o = k * 256 + t;               // f4 idx : (jj, c4)
        int jj = o >> 3, c4 = o & 7;
        float4 w4 = ((const float4*)Wo)[((j0 + jj) * 256 + e0) / 4 + c4];
        *(float4*)&s_wo[jj * 32 + c4 * 4] = w4;
    }
    __syncthreads();

    int w = t >> 5, lane = t & 31;
    int bg = lane >> 2, eg = lane & 3;
    int jj0 = w * 16;

    ull acc[4][4];
#pragma unroll
    for (int i = 0; i < 4; i++)
#pragma unroll
        for (int p = 0; p < 4; p++) acc[i][p] = 0ull;

#pragma unroll
    for (int ju = 0; ju < 16; ju += 4) {
        int j = jj0 + ju;
        float4 p_b[4];
#pragma unroll
        for (int i = 0; i < 4; i++)
            p_b[i] = *(const float4*)&s_p[(bg * 4 + i) * 132 + j];
#pragma unroll
        for (int u = 0; u < 4; u++) {
            float4 wo0 = *(const float4*)&s_wo[(j + u) * 32 + eg * 8];
            float4 wo1 = *(const float4*)&s_wo[(j + u) * 32 + eg * 8 + 4];
            ull w01 = pk(wo0.x, wo0.y), w23 = pk(wo0.z, wo0.w);
            ull w45 = pk(wo1.x, wo1.y), w67 = pk(wo1.z, wo1.w);
#pragma unroll
            for (int i = 0; i < 4; i++) {
                float ps = (&p_b[i].x)[u];
                ull ps2 = pk(ps, ps);
                acc[i][0] = ffma2(ps2, w01, acc[i][0]);
                acc[i][1] = ffma2(ps2, w23, acc[i][1]);
                acc[i][2] = ffma2(ps2, w45, acc[i][2]);
                acc[i][3] = ffma2(ps2, w67, acc[i][3]);
            }
        }
    }

#define OUT_STORE(st) do { \
    _Pragma("unroll") for (int i = 0; i < 4; i++) \
    _Pragma("unroll") for (int p = 0; p < 4; p++) \
        s_red[st][i * 4 + p][lane] = acc[i][p]; } while (0)
#define OUT_ADD(st) do { \
    _Pragma("unroll") for (int i = 0; i < 4; i++) \
    _Pragma("unroll") for (int p = 0; p < 4; p++) \
        acc[i][p] = addf2(acc[i][p], s_red[st][i * 4 + p][lane]); } while (0)

    if (w >= 4) OUT_STORE(w - 4);
    __syncthreads();
    if (w < 4) OUT_ADD(w);
    __syncthreads();
    if (w == 2 || w == 3) OUT_STORE(w - 2);
    __syncthreads();
    if (w < 2) OUT_ADD(w);
    __syncthreads();
    if (w == 1) OUT_STORE(0);
    __syncthreads();
    if (w == 0) {
        OUT_ADD(0);
#pragma unroll
        for (int i = 0; i < 4; i++) {
            int b = bg * 4 + i;
            float* op = out + b * 256 + e0 + eg * 8;
#pragma unroll
            for (int p = 0; p < 4; p++) {
                float2 v = upk(acc[i][p]);
                atomicAdd(op + p * 2 + 0, v.x);
                atomicAdd(op + p * 2 + 1, v.y);
            }
        }
    }
#undef OUT_STORE
#undef OUT_ADD
}

extern "C" void kernel_launch(void* const* d_in, const int* in_sizes, int n_in,
                              void* d_out, int out_size) {
    const float* x     = (const float*)d_in[0];
    const float* Wk    = (const float*)d_in[1];
    // d_in[2] = bk: constant shift per (b,h) across s -> softmax-invariant, unused
    const float* Wv    = (const float*)d_in[3];
    const float* bv    = (const float*)d_in[4];
    const float* query = (const float*)d_in[5];
    const float* Wo    = (const float*)d_in[6];
    const float* bo    = (const float*)d_in[7];
    float* out = (float*)d_out;

    k_wq<<<256, 256>>>(Wk, query);
    k_scores<<<1024, 256>>>(x);      // also zeroes g_xa
    k_xapart<<<512, 256>>>(x);       // atomic-accumulates into g_xa
    k_pooled<<<256, 256>>>(Wv, bv, out, bo);  // output-split, no atomics
    k_out<<<128, 256>>>(Wo, out);
}